// round 4
// baseline (speedup 1.0000x reference)
#include <cuda_runtime.h>
#include <cuda_bf16.h>
#include <cstdint>

// embeddings [B=512, I=128, D=64] fp32
// out[b,i,d] = tanh( emb[b,i,d] * (1/I) * sum_j emb[b,j,d] )
//
// R4: two-pass, barrier-free apply.
//  Pass 1: per-batch column means -> __device__ scratch (128 KB, L2-hot).
//  Pass 2: pure streaming elementwise tanh(in * mean): no smem, no
//  __syncthreads, 4 independent LDG.128 per thread, MUFU overlaps loads.
// R1-R3 showed identical ~8.5us across 3 different memory paths => the
// binder was the in-CTA load->barrier->reduce->barrier->MUFU chain, which
// this removes.

static constexpr int BATCH   = 512;
static constexpr int SEQ_I   = 128;
static constexpr int DIM     = 64;
static constexpr int F4_ROW  = DIM / 4;                      // 16
static constexpr int F4_PER_BATCH = SEQ_I * F4_ROW;          // 2048
static constexpr int TOTAL_F4 = BATCH * F4_PER_BATCH;        // 1,048,576

__device__ float4 g_mean4[BATCH * F4_ROW];                   // 128 KB scratch

__device__ __forceinline__ float fast_tanh(float x) {
    float y;
    asm("tanh.approx.f32 %0, %1;" : "=f"(y) : "f"(x));
    return y;
}

// ---------------- Pass 1: column means ----------------
// One CTA per batch, 256 threads; thread t owns f4-column c=t%16,
// row-group rg=t/16; 8 strided f4 loads -> partial; 16x16 smem reduce.
__global__ __launch_bounds__(256, 8)
void mean_kernel(const float4* __restrict__ in) {
    const int b = blockIdx.x;
    const int t = threadIdx.x;

    const float4* src = in + (size_t)b * F4_PER_BATCH;

    float4 s = make_float4(0.f, 0.f, 0.f, 0.f);
#pragma unroll
    for (int k = 0; k < 8; k++) {
        float4 v = src[t + 256 * k];
        s.x += v.x; s.y += v.y; s.z += v.z; s.w += v.w;
    }

    __shared__ float4 part[256];
    part[t] = s;
    __syncthreads();

    if (t < F4_ROW) {
        float4 m = part[t];
#pragma unroll
        for (int r = 1; r < 16; r++) {
            float4 p = part[t + 16 * r];
            m.x += p.x; m.y += p.y; m.z += p.z; m.w += p.w;
        }
        const float inv = 1.0f / (float)SEQ_I;
        m.x *= inv; m.y *= inv; m.z *= inv; m.w *= inv;
        g_mean4[b * F4_ROW + t] = m;
    }
}

// ---------------- Pass 2: streaming apply ----------------
// 1024 CTAs x 256 threads x 4 f4. CTA covers f4 range [cta*1024, +1024),
// which lies inside one batch (2048 f4/batch). Column c = t%16 invariant
// across the 4 chunks (256 % 16 == 0) -> one mean load per thread.
__global__ __launch_bounds__(256, 8)
void apply_kernel(const float4* __restrict__ in, float4* __restrict__ out) {
    const int t    = threadIdx.x;
    const size_t f0 = (size_t)blockIdx.x * 1024 + t;
    const int b    = blockIdx.x >> 1;            // 2 CTAs per batch

    const float4 m = g_mean4[b * F4_ROW + (t & 15)];

    float4 v[4];
#pragma unroll
    for (int k = 0; k < 4; k++) v[k] = in[f0 + 256 * k];

#pragma unroll
    for (int k = 0; k < 4; k++) {
        float4 r;
        r.x = fast_tanh(v[k].x * m.x);
        r.y = fast_tanh(v[k].y * m.y);
        r.z = fast_tanh(v[k].z * m.z);
        r.w = fast_tanh(v[k].w * m.w);
        out[f0 + 256 * k] = r;
    }
}

extern "C" void kernel_launch(void* const* d_in, const int* in_sizes, int n_in,
                              void* d_out, int out_size) {
    const float4* in  = (const float4*)d_in[0];
    float4*       out = (float4*)d_out;
    mean_kernel<<<BATCH, 256>>>(in);
    apply_kernel<<<TOTAL_F4 / 1024, 256>>>(in, out);
}

// round 5
// speedup vs baseline: 1.1929x; 1.1929x over previous
#include <cuda_runtime.h>
#include <cuda_bf16.h>

// embeddings [B=512, I=128, D=64] fp32
// out[b,i,d] = tanh( emb[b,i,d] * (1/I) * sum_j emb[b,j,d] )
//
// R5: single kernel, SINGLE barrier, minimal critical path.
// Column-split: 2 CTAs per batch (8 f4-columns each), 1024 CTAs x 256 thr,
// single wave at occ 8. Per thread: 4 independent LDG.128 (rows rg+32k),
// warp shuffle xor(8,16) -> per-warp column sums, publish 8x8 f4 to smem,
// ONE __syncthreads, then every thread redundantly sums the 8 warp partials
// (broadcast LDS, conflict-free) -> mean, tanh, 4 coalesced STG.128.
// No serialized reduce thread, no second barrier.

static constexpr int BATCH   = 512;
static constexpr int SEQ_I   = 128;
static constexpr int F4_ROW  = 16;       // 64 floats / 4
static constexpr int F4_COLS = 8;        // f4 columns per CTA chunk
static constexpr int THREADS = 256;

__device__ __forceinline__ float fast_tanh(float x) {
    float y;
    asm("tanh.approx.f32 %0, %1;" : "=f"(y) : "f"(x));
    return y;
}

__global__ __launch_bounds__(THREADS, 8)
void ATT0_40707700032104_kernel(const float4* __restrict__ in,
                                float4* __restrict__ out) {
    const int b    = blockIdx.x >> 1;
    const int half = blockIdx.x & 1;
    const int t    = threadIdx.x;
    const int c    = t & (F4_COLS - 1);   // f4 column in chunk (0..7)
    const int rg   = t >> 3;              // base row (0..31)
    const int w    = t >> 5;              // warp id (0..7)

    // f4 element offset of (row rg, col c) in this batch
    const size_t base = (size_t)b * (SEQ_I * F4_ROW) + half * F4_COLS + c;
    const float4* src = in  + base;
    float4*       dst = out + base;

    // ---- 4 independent coalesced LDG.128 (rows rg + 32k), kept in regs ----
    float4 v[4];
#pragma unroll
    for (int k = 0; k < 4; k++)
        v[k] = src[(size_t)(rg + 32 * k) * F4_ROW];

    float4 s;
    s.x = (v[0].x + v[1].x) + (v[2].x + v[3].x);
    s.y = (v[0].y + v[1].y) + (v[2].y + v[3].y);
    s.z = (v[0].z + v[1].z) + (v[2].z + v[3].z);
    s.w = (v[0].w + v[1].w) + (v[2].w + v[3].w);

    // ---- Warp reduce: lanes l, l+8, l+16, l+24 share column c ----
#pragma unroll
    for (int off = 8; off <= 16; off <<= 1) {
        s.x += __shfl_xor_sync(0xffffffffu, s.x, off);
        s.y += __shfl_xor_sync(0xffffffffu, s.y, off);
        s.z += __shfl_xor_sync(0xffffffffu, s.z, off);
        s.w += __shfl_xor_sync(0xffffffffu, s.w, off);
    }

    // ---- Publish per-warp column sums; ONE barrier ----
    __shared__ float4 wsum[8][F4_COLS];
    if ((t & 31) < F4_COLS) wsum[w][t & 31] = s;
    __syncthreads();

    // ---- Redundant per-thread final reduce (broadcast LDS, no 2nd barrier) ----
    float4 p0 = wsum[0][c], p1 = wsum[1][c], p2 = wsum[2][c], p3 = wsum[3][c];
    float4 p4 = wsum[4][c], p5 = wsum[5][c], p6 = wsum[6][c], p7 = wsum[7][c];
    const float inv = 1.0f / (float)SEQ_I;
    float4 m;
    m.x = (((p0.x + p1.x) + (p2.x + p3.x)) + ((p4.x + p5.x) + (p6.x + p7.x))) * inv;
    m.y = (((p0.y + p1.y) + (p2.y + p3.y)) + ((p4.y + p5.y) + (p6.y + p7.y))) * inv;
    m.z = (((p0.z + p1.z) + (p2.z + p3.z)) + ((p4.z + p5.z) + (p6.z + p7.z))) * inv;
    m.w = (((p0.w + p1.w) + (p2.w + p3.w)) + ((p4.w + p5.w) + (p6.w + p7.w))) * inv;

    // ---- tanh(v * mean) from registers, 4 coalesced STG.128 ----
#pragma unroll
    for (int k = 0; k < 4; k++) {
        float4 r;
        r.x = fast_tanh(v[k].x * m.x);
        r.y = fast_tanh(v[k].y * m.y);
        r.z = fast_tanh(v[k].z * m.z);
        r.w = fast_tanh(v[k].w * m.w);
        dst[(size_t)(rg + 32 * k) * F4_ROW] = r;
    }
}

extern "C" void kernel_launch(void* const* d_in, const int* in_sizes, int n_in,
                              void* d_out, int out_size) {
    const float4* in  = (const float4*)d_in[0];
    float4*       out = (float4*)d_out;
    ATT0_40707700032104_kernel<<<BATCH * 2, THREADS>>>(in, out);
}